// round 1
// baseline (speedup 1.0000x reference)
#include <cuda_runtime.h>
#include <math.h>

#define K_CODES 2048
#define D_DIM   64
#define N_VEC   65536
#define BN      128            // rows per block
#define BK      128            // codes per chunk
#define NTHREADS 256
#define NBLOCKS (N_VEC / BN)   // 512
#define SMEM_FLOATS (8192 + 8192 + 128 + 128 + 128)
#define SMEM_BYTES  (SMEM_FLOATS * 4)

__device__ float g_c2[K_CODES];
__device__ int   g_counts[K_CODES];
__device__ float g_partial[NBLOCKS];

// ---- packed fp32x2 helpers (sm_103a FFMA2 path, PTX-only per SASS_QUICKREF) ----
__device__ __forceinline__ unsigned long long pk2(float x) {
    unsigned long long r;
    asm("mov.b64 %0, {%1, %1};" : "=l"(r) : "f"(x));
    return r;
}
__device__ __forceinline__ void fma2(unsigned long long& acc,
                                     unsigned long long a, unsigned long long b) {
    asm("fma.rn.f32x2 %0, %1, %2, %0;" : "+l"(acc) : "l"(a), "l"(b));
}
__device__ __forceinline__ void upk(unsigned long long v, float& lo, float& hi) {
    asm("mov.b64 {%0, %1}, %2;" : "=f"(lo), "=f"(hi) : "l"(v));
}

// ---- kernel A: zero histogram, precompute ||c_k||^2 ----
__global__ void vq_prep(const float* __restrict__ cb) {
    int k = blockIdx.x * blockDim.x + threadIdx.x;
    if (k < K_CODES) {
        float s = 0.f;
        #pragma unroll
        for (int d = 0; d < D_DIM; d++) {
            float v = cb[d * K_CODES + k];
            s = fmaf(v, v, s);
        }
        g_c2[k] = s;
        g_counts[k] = 0;
    }
}

// ---- kernel B: fused GEMM + argmin + gather + partial stats ----
__global__ __launch_bounds__(NTHREADS) void vq_main(
    const float* __restrict__ x, const float* __restrict__ cb, float* __restrict__ out)
{
    extern __shared__ float sm[];
    float* xs    = sm;                 // [64][128] transposed x tile
    float* cs    = sm + 8192;          // [64][128] codebook chunk
    float* x2s   = sm + 16384;         // [128]
    float* serr  = sm + 16512;         // [128]
    int*   sbidx = (int*)(sm + 16640); // [128]
    float* rs    = cs;                 // reuse cs region after main loop: [128][16]
    int*   ri    = (int*)(cs + 2048);  // [128][16]

    const int tid = threadIdx.x;
    const int tx  = tid & 15;          // k-group 0..15
    const int ty  = tid >> 4;          // n-group 0..15
    const int n0  = blockIdx.x * BN;

    // load x tile transposed: xs[d][n]
    {
        int r = tid >> 1;              // row 0..127
        int half = tid & 1;
        const float4* src = (const float4*)(x + (size_t)(n0 + r) * D_DIM + half * 32);
        #pragma unroll
        for (int i = 0; i < 8; i++) {
            float4 v = src[i];
            int c = half * 32 + i * 4;
            xs[(c + 0) * BN + r] = v.x;
            xs[(c + 1) * BN + r] = v.y;
            xs[(c + 2) * BN + r] = v.z;
            xs[(c + 3) * BN + r] = v.w;
        }
    }
    __syncthreads();
    if (tid < BN) {
        float s = 0.f;
        #pragma unroll
        for (int d = 0; d < D_DIM; d++) { float v = xs[d * BN + tid]; s = fmaf(v, v, s); }
        x2s[tid] = s;
    }

    float best[8];
    int   bidx[8];
    #pragma unroll
    for (int i = 0; i < 8; i++) { best[i] = 3.4e38f; bidx[i] = 0; }

    for (int kc = 0; kc < K_CODES / BK; kc++) {
        __syncthreads();
        // stage codebook chunk: cs[d][k]
        {
            int dr = tid >> 2;
            int part = tid & 3;
            const float4* src = (const float4*)(cb + (size_t)dr * K_CODES + kc * BK + part * 32);
            float4* dst = (float4*)(cs + dr * BK + part * 32);
            #pragma unroll
            for (int i = 0; i < 8; i++) dst[i] = src[i];
        }
        __syncthreads();

        unsigned long long acc[8][4];
        #pragma unroll
        for (int i = 0; i < 8; i++)
            #pragma unroll
            for (int j = 0; j < 4; j++) acc[i][j] = 0ULL;

        #pragma unroll 4
        for (int d = 0; d < D_DIM; d++) {
            const float4* ap = (const float4*)(xs + d * BN + ty * 8);
            float4 a0 = ap[0], a1 = ap[1];
            const ulonglong2* bp = (const ulonglong2*)(cs + d * BK + tx * 8);
            ulonglong2 b01 = bp[0], b23 = bp[1];
            unsigned long long bu[4] = {b01.x, b01.y, b23.x, b23.y};
            float av[8] = {a0.x, a0.y, a0.z, a0.w, a1.x, a1.y, a1.z, a1.w};
            #pragma unroll
            for (int i = 0; i < 8; i++) {
                unsigned long long ad = pk2(av[i]);
                #pragma unroll
                for (int j = 0; j < 4; j++) fma2(acc[i][j], ad, bu[j]);
            }
        }

        // scores: c2[k] - 2*dot ; keep running argmin (first-occurrence on ties)
        const int kbase = kc * BK + tx * 8;
        float c2v[8];
        #pragma unroll
        for (int j = 0; j < 8; j++) c2v[j] = g_c2[kbase + j];
        #pragma unroll
        for (int i = 0; i < 8; i++) {
            #pragma unroll
            for (int j = 0; j < 4; j++) {
                float lo, hi;
                upk(acc[i][j], lo, hi);
                float s0 = fmaf(-2.f, lo, c2v[2 * j]);
                float s1 = fmaf(-2.f, hi, c2v[2 * j + 1]);
                if (s0 < best[i]) { best[i] = s0; bidx[i] = kbase + 2 * j; }
                if (s1 < best[i]) { best[i] = s1; bidx[i] = kbase + 2 * j + 1; }
            }
        }
    }

    __syncthreads();   // done reading cs; reuse as reduction scratch
    #pragma unroll
    for (int i = 0; i < 8; i++) {
        rs[(ty * 8 + i) * 16 + tx] = best[i];
        ri[(ty * 8 + i) * 16 + tx] = bidx[i];
    }
    __syncthreads();

    if (tid < BN) {
        float bs = rs[tid * 16];
        int   bi = ri[tid * 16];
        #pragma unroll
        for (int t = 1; t < 16; t++) {
            float s = rs[tid * 16 + t];
            int  ii = ri[tid * 16 + t];
            if (s < bs || (s == bs && ii < bi)) { bs = s; bi = ii; }
        }
        sbidx[tid] = bi;
        serr[tid] = x2s[tid] + bs;          // = ||x - q||^2
        atomicAdd(&g_counts[bi], 1);        // integer atomic: deterministic
    }
    __syncthreads();

    // deterministic tree reduction of squared errors
    for (int s = 64; s > 0; s >>= 1) {
        if (tid < s) serr[tid] += serr[tid + s];
        __syncthreads();
    }
    if (tid == 0) g_partial[blockIdx.x] = serr[0];

    // write ste = quantized vectors (gather codebook columns)
    #pragma unroll
    for (int it = 0; it < (BN * D_DIM) / NTHREADS; it++) {
        int idx = it * NTHREADS + tid;
        int n = idx >> 6, d = idx & 63;
        out[(size_t)(n0 + n) * D_DIM + d] = cb[(size_t)d * K_CODES + sbidx[n]];
    }
}

// ---- kernel C: finalize scalars (deterministic fixed-order reductions) ----
__global__ void vq_finalize(float* __restrict__ out) {
    __shared__ float sd[1024];
    int t = threadIdx.x;

    float v = (t < NBLOCKS) ? g_partial[t] : 0.f;
    sd[t] = v;
    __syncthreads();
    for (int s = 512; s > 0; s >>= 1) { if (t < s) sd[t] += sd[t + s]; __syncthreads(); }
    float mse = sd[0] / (float)(N_VEC * D_DIM);
    __syncthreads();

    const float invN = 1.f / (float)N_VEC;
    float p0 = (float)g_counts[t] * invN;
    float p1 = (float)g_counts[t + 1024] * invN;
    float term = p0 * logf(p0 + 1e-10f) + p1 * logf(p1 + 1e-10f);
    sd[t] = term;
    __syncthreads();
    for (int s = 512; s > 0; s >>= 1) { if (t < s) sd[t] += sd[t + s]; __syncthreads(); }

    if (t == 0) {
        out[(size_t)N_VEC * D_DIM + 0] = expf(-sd[0]);   // perplexity
        out[(size_t)N_VEC * D_DIM + 1] = mse;            // codebook_loss
        out[(size_t)N_VEC * D_DIM + 2] = 0.25f * mse;    // commitment_loss
    }
}

extern "C" void kernel_launch(void* const* d_in, const int* in_sizes, int n_in,
                              void* d_out, int out_size) {
    const float* a = (const float*)d_in[0];
    const float* b = (const float*)d_in[1];
    const float* x  = a;
    const float* cb = b;
    if (n_in >= 2 && in_sizes[0] < in_sizes[1]) { x = b; cb = a; }  // defensive order check
    float* out = (float*)d_out;

    cudaFuncSetAttribute(vq_main, cudaFuncAttributeMaxDynamicSharedMemorySize, SMEM_BYTES);

    vq_prep<<<K_CODES / 256, 256>>>(cb);
    vq_main<<<NBLOCKS, NTHREADS, SMEM_BYTES>>>(x, cb, out);
    vq_finalize<<<1, 1024>>>(out);
}

// round 2
// speedup vs baseline: 1.0003x; 1.0003x over previous
#include <cuda_runtime.h>
#include <math.h>

#define K_CODES 2048
#define D_DIM   64
#define N_VEC   65536
#define BN      128            // rows per block
#define BK      128            // codes per chunk
#define NTHREADS 256
#define NBLOCKS (N_VEC / BN)   // 512
#define SMEM_FLOATS (8192 + 8192 + 128 + 128 + 128)
#define SMEM_BYTES  (SMEM_FLOATS * 4)

__device__ float g_c2[K_CODES];
__device__ int   g_counts[K_CODES];
__device__ float g_partial[NBLOCKS];

// ---- packed fp32x2 helpers (sm_103a FFMA2 path, PTX-only per SASS_QUICKREF) ----
__device__ __forceinline__ unsigned long long pk2(float x) {
    unsigned long long r;
    asm("mov.b64 %0, {%1, %1};" : "=l"(r) : "f"(x));
    return r;
}
__device__ __forceinline__ void fma2(unsigned long long& acc,
                                     unsigned long long a, unsigned long long b) {
    asm("fma.rn.f32x2 %0, %1, %2, %0;" : "+l"(acc) : "l"(a), "l"(b));
}
__device__ __forceinline__ void upk(unsigned long long v, float& lo, float& hi) {
    asm("mov.b64 {%0, %1}, %2;" : "=f"(lo), "=f"(hi) : "l"(v));
}

// ---- kernel A: zero histogram, precompute ||c_k||^2 ----
__global__ void vq_prep(const float* __restrict__ cb) {
    int k = blockIdx.x * blockDim.x + threadIdx.x;
    if (k < K_CODES) {
        float s = 0.f;
        #pragma unroll
        for (int d = 0; d < D_DIM; d++) {
            float v = cb[d * K_CODES + k];
            s = fmaf(v, v, s);
        }
        g_c2[k] = s;
        g_counts[k] = 0;
    }
}

// ---- kernel B: fused GEMM + argmin + gather + partial stats ----
__global__ __launch_bounds__(NTHREADS) void vq_main(
    const float* __restrict__ x, const float* __restrict__ cb, float* __restrict__ out)
{
    extern __shared__ float sm[];
    float* xs    = sm;                 // [64][128] transposed x tile
    float* cs    = sm + 8192;          // [64][128] codebook chunk
    float* x2s   = sm + 16384;         // [128]
    float* serr  = sm + 16512;         // [128]
    int*   sbidx = (int*)(sm + 16640); // [128]
    float* rs    = cs;                 // reuse cs region after main loop: [128][16]
    int*   ri    = (int*)(cs + 2048);  // [128][16]

    const int tid = threadIdx.x;
    const int tx  = tid & 15;          // k-group 0..15
    const int ty  = tid >> 4;          // n-group 0..15
    const int n0  = blockIdx.x * BN;

    // load x tile transposed: xs[d][n]
    {
        int r = tid >> 1;              // row 0..127
        int half = tid & 1;
        const float4* src = (const float4*)(x + (size_t)(n0 + r) * D_DIM + half * 32);
        #pragma unroll
        for (int i = 0; i < 8; i++) {
            float4 v = src[i];
            int c = half * 32 + i * 4;
            xs[(c + 0) * BN + r] = v.x;
            xs[(c + 1) * BN + r] = v.y;
            xs[(c + 2) * BN + r] = v.z;
            xs[(c + 3) * BN + r] = v.w;
        }
    }
    __syncthreads();
    if (tid < BN) {
        float s = 0.f;
        #pragma unroll
        for (int d = 0; d < D_DIM; d++) { float v = xs[d * BN + tid]; s = fmaf(v, v, s); }
        x2s[tid] = s;
    }

    float best[8];
    int   bidx[8];
    #pragma unroll
    for (int i = 0; i < 8; i++) { best[i] = 3.4e38f; bidx[i] = 0; }

    for (int kc = 0; kc < K_CODES / BK; kc++) {
        __syncthreads();
        // stage codebook chunk: cs[d][k]
        {
            int dr = tid >> 2;
            int part = tid & 3;
            const float4* src = (const float4*)(cb + (size_t)dr * K_CODES + kc * BK + part * 32);
            float4* dst = (float4*)(cs + dr * BK + part * 32);
            #pragma unroll
            for (int i = 0; i < 8; i++) dst[i] = src[i];
        }
        __syncthreads();

        unsigned long long acc[8][4];
        #pragma unroll
        for (int i = 0; i < 8; i++)
            #pragma unroll
            for (int j = 0; j < 4; j++) acc[i][j] = 0ULL;

        #pragma unroll 4
        for (int d = 0; d < D_DIM; d++) {
            const float4* ap = (const float4*)(xs + d * BN + ty * 8);
            float4 a0 = ap[0], a1 = ap[1];
            const ulonglong2* bp = (const ulonglong2*)(cs + d * BK + tx * 8);
            ulonglong2 b01 = bp[0], b23 = bp[1];
            unsigned long long bu[4] = {b01.x, b01.y, b23.x, b23.y};
            float av[8] = {a0.x, a0.y, a0.z, a0.w, a1.x, a1.y, a1.z, a1.w};
            #pragma unroll
            for (int i = 0; i < 8; i++) {
                unsigned long long ad = pk2(av[i]);
                #pragma unroll
                for (int j = 0; j < 4; j++) fma2(acc[i][j], ad, bu[j]);
            }
        }

        // scores: c2[k] - 2*dot ; keep running argmin (first-occurrence on ties)
        const int kbase = kc * BK + tx * 8;
        float c2v[8];
        #pragma unroll
        for (int j = 0; j < 8; j++) c2v[j] = g_c2[kbase + j];
        #pragma unroll
        for (int i = 0; i < 8; i++) {
            #pragma unroll
            for (int j = 0; j < 4; j++) {
                float lo, hi;
                upk(acc[i][j], lo, hi);
                float s0 = fmaf(-2.f, lo, c2v[2 * j]);
                float s1 = fmaf(-2.f, hi, c2v[2 * j + 1]);
                if (s0 < best[i]) { best[i] = s0; bidx[i] = kbase + 2 * j; }
                if (s1 < best[i]) { best[i] = s1; bidx[i] = kbase + 2 * j + 1; }
            }
        }
    }

    __syncthreads();   // done reading cs; reuse as reduction scratch
    #pragma unroll
    for (int i = 0; i < 8; i++) {
        rs[(ty * 8 + i) * 16 + tx] = best[i];
        ri[(ty * 8 + i) * 16 + tx] = bidx[i];
    }
    __syncthreads();

    if (tid < BN) {
        float bs = rs[tid * 16];
        int   bi = ri[tid * 16];
        #pragma unroll
        for (int t = 1; t < 16; t++) {
            float s = rs[tid * 16 + t];
            int  ii = ri[tid * 16 + t];
            if (s < bs || (s == bs && ii < bi)) { bs = s; bi = ii; }
        }
        sbidx[tid] = bi;
        serr[tid] = x2s[tid] + bs;          // = ||x - q||^2
        atomicAdd(&g_counts[bi], 1);        // integer atomic: deterministic
    }
    __syncthreads();

    // deterministic tree reduction of squared errors
    for (int s = 64; s > 0; s >>= 1) {
        if (tid < s) serr[tid] += serr[tid + s];
        __syncthreads();
    }
    if (tid == 0) g_partial[blockIdx.x] = serr[0];

    // write ste = quantized vectors (gather codebook columns)
    #pragma unroll
    for (int it = 0; it < (BN * D_DIM) / NTHREADS; it++) {
        int idx = it * NTHREADS + tid;
        int n = idx >> 6, d = idx & 63;
        out[(size_t)(n0 + n) * D_DIM + d] = cb[(size_t)d * K_CODES + sbidx[n]];
    }
}

// ---- kernel C: finalize scalars (deterministic fixed-order reductions) ----
__global__ void vq_finalize(float* __restrict__ out) {
    __shared__ float sd[1024];
    int t = threadIdx.x;

    float v = (t < NBLOCKS) ? g_partial[t] : 0.f;
    sd[t] = v;
    __syncthreads();
    for (int s = 512; s > 0; s >>= 1) { if (t < s) sd[t] += sd[t + s]; __syncthreads(); }
    float mse = sd[0] / (float)(N_VEC * D_DIM);
    __syncthreads();

    const float invN = 1.f / (float)N_VEC;
    float p0 = (float)g_counts[t] * invN;
    float p1 = (float)g_counts[t + 1024] * invN;
    float term = p0 * logf(p0 + 1e-10f) + p1 * logf(p1 + 1e-10f);
    sd[t] = term;
    __syncthreads();
    for (int s = 512; s > 0; s >>= 1) { if (t < s) sd[t] += sd[t + s]; __syncthreads(); }

    if (t == 0) {
        out[(size_t)N_VEC * D_DIM + 0] = expf(-sd[0]);   // perplexity
        out[(size_t)N_VEC * D_DIM + 1] = mse;            // codebook_loss
        out[(size_t)N_VEC * D_DIM + 2] = 0.25f * mse;    // commitment_loss
    }
}

extern "C" void kernel_launch(void* const* d_in, const int* in_sizes, int n_in,
                              void* d_out, int out_size) {
    const float* a = (const float*)d_in[0];
    const float* b = (const float*)d_in[1];
    const float* x  = a;
    const float* cb = b;
    if (n_in >= 2 && in_sizes[0] < in_sizes[1]) { x = b; cb = a; }  // defensive order check
    float* out = (float*)d_out;

    cudaFuncSetAttribute(vq_main, cudaFuncAttributeMaxDynamicSharedMemorySize, SMEM_BYTES);

    vq_prep<<<K_CODES / 256, 256>>>(cb);
    vq_main<<<NBLOCKS, NTHREADS, SMEM_BYTES>>>(x, cb, out);
    vq_finalize<<<1, 1024>>>(out);
}

// round 4
// speedup vs baseline: 1.4277x; 1.4272x over previous
#include <cuda_runtime.h>
#include <cuda_bf16.h>
#include <cstdint>
#include <math.h>

#define K_CODES 2048
#define D_DIM   64
#define N_VEC   65536
#define M_TILE  256
#define NTILE   128
#define NT_CNT  (K_CODES / NTILE)     // 16
#define NTHREADS 256
#define NBLOCKS (N_VEC / M_TILE)      // 256

// ---- smem layout (bytes) ----
#define SM_X2   0                     // 256 floats
#define SM_IDX  1024                  // 256 ints
#define SM_A    4096                  // 3 splits x 256 rows x 128B
#define SPLIT_A 32768
#define SM_B    (SM_A + 3 * SPLIT_A)  // 102400; 2 stages x 3 splits x 16KB
#define SPLIT_B 16384
#define STAGE_B (3 * SPLIT_B)
#define SMEM_TOTAL (SM_B + 2 * STAGE_B)   // 200704
// reduction scratch reuses B region after mainloop:
#define SM_RS   SM_B                  // 256*8 floats
#define SM_RI   (SM_B + 8192)         // 256*8 ints
#define SM_RED  (SM_B + 16384)        // 256 floats

__device__ __align__(256) __nv_bfloat16 g_cb0[K_CODES * D_DIM];
__device__ __align__(256) __nv_bfloat16 g_cb1[K_CODES * D_DIM];
__device__ __align__(256) __nv_bfloat16 g_cb2[K_CODES * D_DIM];
__device__ __align__(256) float g_cbT[K_CODES * D_DIM];   // [k][d] fp32 for gather
__device__ float    g_cn2[K_CODES];
__device__ int      g_counts[K_CODES];
__device__ float    g_partial[NBLOCKS];
__device__ unsigned g_ticket;

// ---- helpers ----
__device__ __forceinline__ void mma16816(float* d, const uint32_t* a, const uint32_t* b) {
    asm volatile("mma.sync.aligned.m16n8k16.row.col.f32.bf16.bf16.f32 "
                 "{%0,%1,%2,%3}, {%4,%5,%6,%7}, {%8,%9}, {%0,%1,%2,%3};"
                 : "+f"(d[0]), "+f"(d[1]), "+f"(d[2]), "+f"(d[3])
                 : "r"(a[0]), "r"(a[1]), "r"(a[2]), "r"(a[3]), "r"(b[0]), "r"(b[1]));
}
#define CP_ASYNC16(dst, src) \
    asm volatile("cp.async.cg.shared.global [%0], [%1], 16;" :: "r"(dst), "l"(src) : "memory")
#define CP_COMMIT()  asm volatile("cp.async.commit_group;" ::: "memory")
#define CP_WAIT1()   asm volatile("cp.async.wait_group 1;" ::: "memory")
#define CP_WAIT0()   asm volatile("cp.async.wait_group 0;" ::: "memory")

__device__ __forceinline__ uint32_t smem_u32(const void* p) {
    uint32_t a;
    asm("{ .reg .u64 t; cvta.to.shared.u64 t, %1; cvt.u32.u64 %0, t; }" : "=r"(a) : "l"(p));
    return a;
}

__device__ __forceinline__ void split3(float v, uint16_t& s0, uint16_t& s1, uint16_t& s2) {
    __nv_bfloat16 h0 = __float2bfloat16_rn(v);
    float r1 = v - __bfloat162float(h0);
    __nv_bfloat16 h1 = __float2bfloat16_rn(r1);
    float r2 = r1 - __bfloat162float(h1);
    __nv_bfloat16 h2 = __float2bfloat16_rn(r2);
    s0 = __bfloat16_as_ushort(h0);
    s1 = __bfloat16_as_ushort(h1);
    s2 = __bfloat16_as_ushort(h2);
}

// ============================ prep kernel ============================
__global__ void vq_prep(const float* __restrict__ cb) {
    int k = blockIdx.x * blockDim.x + threadIdx.x;
    if (k < K_CODES) {
        float s = 0.f;
        #pragma unroll 8
        for (int d = 0; d < D_DIM; d++) {
            float v = cb[(size_t)d * K_CODES + k];
            s = fmaf(v, v, s);
            g_cbT[(size_t)k * D_DIM + d] = v;
            uint16_t a0, a1, a2;
            split3(v, a0, a1, a2);
            g_cb0[(size_t)k * D_DIM + d] = __ushort_as_bfloat16(a0);
            g_cb1[(size_t)k * D_DIM + d] = __ushort_as_bfloat16(a1);
            g_cb2[(size_t)k * D_DIM + d] = __ushort_as_bfloat16(a2);
        }
        g_cn2[k] = s;
        g_counts[k] = 0;
    }
    if (k == 0) g_ticket = 0;
}

// ============================ main kernel ============================
__device__ __forceinline__ void load_b_tile(char* smc, int tile, int stage, int tid) {
    const __nv_bfloat16* srcs[3] = { g_cb0, g_cb1, g_cb2 };
    uint32_t base = smem_u32(smc + SM_B + stage * STAGE_B);
    #pragma unroll
    for (int it = 0; it < 12; it++) {                 // 3072 16B chunks / 256 thr
        int v = it * NTHREADS + tid;
        int p = v >> 10;                              // split 0..2
        int r = (v >> 3) & 127;                       // code row in tile
        int c = v & 7;                                // 16B chunk
        const __nv_bfloat16* src = srcs[p] + ((size_t)(tile * NTILE + r)) * D_DIM + c * 8;
        uint32_t dst = base + p * SPLIT_B + r * 128 + ((c ^ (r & 7)) << 4);
        CP_ASYNC16(dst, src);
    }
}

__global__ __launch_bounds__(NTHREADS) void vq_main(
    const float* __restrict__ x, float* __restrict__ out)
{
    extern __shared__ char smc[];
    const int tid = threadIdx.x;
    const int lane = tid & 31, warp = tid >> 5;
    const int mw = warp >> 1, nw = warp & 1;          // 4 M-warps x 2 N-warps
    const int qr = lane >> 2, qc = lane & 3;          // frag row / col quads
    float* x2s  = (float*)(smc + SM_X2);
    int*   sidx = (int*)(smc + SM_IDX);

    // ---- convert this CTA's 256-row x tile into 3 bf16 splits (swizzled) ----
    {
        const float* xrow = x + ((size_t)blockIdx.x * M_TILE + tid) * D_DIM;
        float x2 = 0.f;
        #pragma unroll
        for (int j = 0; j < 8; j++) {                 // 8 chunks of 8 floats
            float4 va = __ldg((const float4*)xrow + j * 2);
            float4 vb = __ldg((const float4*)xrow + j * 2 + 1);
            float f[8] = { va.x, va.y, va.z, va.w, vb.x, vb.y, vb.z, vb.w };
            uint16_t s0[8], s1[8], s2[8];
            #pragma unroll
            for (int e = 0; e < 8; e++) {
                x2 = fmaf(f[e], f[e], x2);
                split3(f[e], s0[e], s1[e], s2[e]);
            }
            uint32_t off = tid * 128 + ((j ^ (tid & 7)) << 4);
            #pragma unroll
            for (int p = 0; p < 3; p++) {
                const uint16_t* sp = (p == 0) ? s0 : (p == 1) ? s1 : s2;
                uint4 w;
                w.x = (uint32_t)sp[1] << 16 | sp[0];
                w.y = (uint32_t)sp[3] << 16 | sp[2];
                w.z = (uint32_t)sp[5] << 16 | sp[4];
                w.w = (uint32_t)sp[7] << 16 | sp[6];
                *(uint4*)(smc + SM_A + p * SPLIT_A + off) = w;
            }
        }
        x2s[tid] = x2;
    }
    __syncthreads();

    // ---- per-thread fragment address bases (swizzle value = qr for A and B) ----
    const int kb = qc * 4;                            // byte offset of (k&7)*2, k=qc*2
    uint32_t cs[8];
    #pragma unroll
    for (int c = 0; c < 8; c++) cs[c] = (uint32_t)((c ^ qr) << 4);
    uint32_t rowA[4];
    #pragma unroll
    for (int mt = 0; mt < 4; mt++)
        rowA[mt] = (uint32_t)((mw * 64 + mt * 16 + qr) * 128 + kb);
    uint32_t rowB[8];
    #pragma unroll
    for (int nt = 0; nt < 8; nt++)
        rowB[nt] = (uint32_t)((nw * 64 + nt * 8 + qr) * 128 + kb);

    const int pa[6] = { 2, 0, 1, 1, 0, 0 };           // small terms first
    const int pb[6] = { 0, 2, 1, 0, 1, 0 };

    float best[8];
    int   bidx[8];
    #pragma unroll
    for (int i = 0; i < 8; i++) { best[i] = 3.4e38f; bidx[i] = 0; }

    load_b_tile(smc, 0, 0, tid); CP_COMMIT();

    for (int t = 0; t < NT_CNT; t++) {
        const int st = t & 1;
        if (t + 1 < NT_CNT) { load_b_tile(smc, t + 1, 1 - st, tid); CP_COMMIT(); CP_WAIT1(); }
        else                { CP_WAIT0(); }
        __syncthreads();

        float acc[4][8][4];
        #pragma unroll
        for (int mt = 0; mt < 4; mt++)
            #pragma unroll
            for (int nt = 0; nt < 8; nt++)
                #pragma unroll
                for (int e = 0; e < 4; e++) acc[mt][nt][e] = 0.f;

        const char* Bst = smc + SM_B + st * STAGE_B;
        #pragma unroll
        for (int p = 0; p < 6; p++) {
            const char* Ab = smc + SM_A + pa[p] * SPLIT_A;
            const char* Bb = Bst + pb[p] * SPLIT_B;
            #pragma unroll
            for (int k4 = 0; k4 < 4; k4++) {          // koff = k4*16
                const uint32_t ca = cs[k4 * 2], cb = cs[k4 * 2 + 1];
                uint32_t bf[8][2];
                #pragma unroll
                for (int nt = 0; nt < 8; nt++) {
                    bf[nt][0] = *(const uint32_t*)(Bb + rowB[nt] + ca);
                    bf[nt][1] = *(const uint32_t*)(Bb + rowB[nt] + cb);
                }
                #pragma unroll
                for (int mt = 0; mt < 4; mt++) {
                    uint32_t af[4];
                    af[0] = *(const uint32_t*)(Ab + rowA[mt] + ca);          // m=qr
                    af[1] = *(const uint32_t*)(Ab + rowA[mt] + 1024 + ca);   // m=qr+8
                    af[2] = *(const uint32_t*)(Ab + rowA[mt] + cb);
                    af[3] = *(const uint32_t*)(Ab + rowA[mt] + 1024 + cb);
                    #pragma unroll
                    for (int nt = 0; nt < 8; nt++)
                        mma16816(acc[mt][nt], af, bf[nt]);
                }
            }
        }

        // ---- epilogue: scores + running argmin ----
        #pragma unroll
        for (int nt = 0; nt < 8; nt++) {
            const int n0 = t * NTILE + nw * 64 + nt * 8 + qc * 2;
            const float2 c2 = __ldg((const float2*)(g_cn2 + n0));
            #pragma unroll
            for (int mt = 0; mt < 4; mt++) {
                #pragma unroll
                for (int h = 0; h < 2; h++) {
                    const int sl = mt * 2 + h;
                    float s0 = fmaf(-2.f, acc[mt][nt][h * 2 + 0], c2.x);
                    float s1 = fmaf(-2.f, acc[mt][nt][h * 2 + 1], c2.y);
                    if (s0 < best[sl]) { best[sl] = s0; bidx[sl] = n0; }
                    if (s1 < best[sl]) { best[sl] = s1; bidx[sl] = n0 + 1; }
                }
            }
        }
        __syncthreads();
    }

    // ---- cross-thread argmin: 8 contributors per row ----
    float* rs = (float*)(smc + SM_RS);
    int*   ri = (int*)(smc + SM_RI);
    float* red = (float*)(smc + SM_RED);
    const int cid = nw * 4 + qc;
    #pragma unroll
    for (int mt = 0; mt < 4; mt++)
        #pragma unroll
        for (int h = 0; h < 2; h++) {
            int m = mw * 64 + mt * 16 + qr + h * 8;
            rs[m * 8 + cid] = best[mt * 2 + h];
            ri[m * 8 + cid] = bidx[mt * 2 + h];
        }
    __syncthreads();

    {
        float bs = rs[tid * 8];
        int   bi = ri[tid * 8];
        #pragma unroll
        for (int c = 1; c < 8; c++) {
            float s = rs[tid * 8 + c];
            int  ii = ri[tid * 8 + c];
            if (s < bs || (s == bs && ii < bi)) { bs = s; bi = ii; }
        }
        sidx[tid] = bi;
        atomicAdd(&g_counts[bi], 1);
        __syncthreads();                  // rs reads done before overwrite
        red[tid] = x2s[tid] + bs;         // ||x - q||^2
    }
    __syncthreads();

    // gather quantized rows (ste == q), coalesced
    #pragma unroll
    for (int it = 0; it < 16; it++) {
        int idx4 = it * NTHREADS + tid;   // 4096 float4s
        int n = idx4 >> 4, d4 = idx4 & 15;
        float4 v = __ldg((const float4*)(g_cbT + (size_t)sidx[n] * D_DIM) + d4);
        ((float4*)(out + ((size_t)blockIdx.x * M_TILE + n) * D_DIM))[d4] = v;
    }

    for (int s = 128; s > 0; s >>= 1) {
        if (tid < s) red[tid] += red[tid + s];
        __syncthreads();
    }
    if (tid == 0) g_partial[blockIdx.x] = red[0];

    // ---- last block finalizes scalars and resets globals ----
    __shared__ int s_last;
    __threadfence();
    if (tid == 0) s_last = (atomicAdd(&g_ticket, 1u) == NBLOCKS - 1);
    __syncthreads();
    if (!s_last) return;
    __threadfence();

    red[tid] = g_partial[tid];            // NBLOCKS == NTHREADS == 256
    __syncthreads();
    for (int s = 128; s > 0; s >>= 1) {
        if (tid < s) red[tid] += red[tid + s];
        __syncthreads();
    }
    float mse = red[0] / (float)((size_t)N_VEC * D_DIM);
    __syncthreads();

    const float invN = 1.f / (float)N_VEC;
    float e = 0.f;
    for (int j = tid; j < K_CODES; j += NTHREADS) {
        float pr = (float)g_counts[j] * invN;
        e += pr * logf(pr + 1e-10f);
    }
    red[tid] = e;
    __syncthreads();
    for (int s = 128; s > 0; s >>= 1) {
        if (tid < s) red[tid] += red[tid + s];
        __syncthreads();
    }
    if (tid == 0) {
        out[(size_t)N_VEC * D_DIM + 0] = expf(-red[0]);   // perplexity
        out[(size_t)N_VEC * D_DIM + 1] = mse;             // codebook_loss
        out[(size_t)N_VEC * D_DIM + 2] = 0.25f * mse;     // commitment_loss
    }
    __syncthreads();
    for (int j = tid; j < K_CODES; j += NTHREADS) g_counts[j] = 0;   // replay reset
    if (tid == 0) g_ticket = 0;
}

// ============================ launcher ============================
extern "C" void kernel_launch(void* const* d_in, const int* in_sizes, int n_in,
                              void* d_out, int out_size) {
    const float* a = (const float*)d_in[0];
    const float* b = (const float*)d_in[1];
    const float* x  = a;
    const float* cb = b;
    if (n_in >= 2 && in_sizes[0] < in_sizes[1]) { x = b; cb = a; }
    float* out = (float*)d_out;

    cudaFuncSetAttribute(vq_main, cudaFuncAttributeMaxDynamicSharedMemorySize, SMEM_TOTAL);

    vq_prep<<<K_CODES / 256, 256>>>(cb);
    vq_main<<<NBLOCKS, NTHREADS, SMEM_TOTAL>>>(x, out);
}